// round 9
// baseline (speedup 1.0000x reference)
#include <cuda_runtime.h>
#include <cuda_bf16.h>
#include <math.h>
#include <stdint.h>

// ---------------- problem constants ----------------
#define TT   4096
#define HH   2048
#define EE   64
#define MM   1408
#define MSS  2816
#define KK   6
#define CC   768
#define NGG  8
#define TGG  3
#define NPAIR (TT*KK)        // 24576

// ---------------- device scratch ----------------
__device__ int   g_topk_i[NPAIR];
__device__ float g_topk_w[NPAIR];
__device__ int   g_cnt[EE];
__device__ int   g_lists[EE*CC];
__device__ float g_gbuf[(size_t)NPAIR*MM];
__device__ float g_ubuf[(size_t)NPAIR*MM];
__device__ float g_hbuf[(size_t)NPAIR*MM];
__device__ float g_outb[(size_t)NPAIR*HH];
__device__ float g_gs[(size_t)TT*MSS];
__device__ float g_us[(size_t)TT*MSS];
__device__ float g_hs[(size_t)TT*MSS];
__device__ float g_ys[(size_t)TT*HH];

// ---------------- gate ----------------
__global__ void gate_kernel(const float* __restrict__ x,
                            const float* __restrict__ gw,
                            int* __restrict__ ti, float* __restrict__ tw)
{
    int t = blockIdx.x;
    __shared__ float xs[HH];
    __shared__ float sc[EE];
    for (int i = threadIdx.x; i < HH; i += 64) xs[i] = x[(size_t)t*HH + i];
    __syncthreads();
    {
        int e = threadIdx.x;
        const float* w = gw + (size_t)e * HH;
        float acc = 0.f;
        #pragma unroll 8
        for (int h = 0; h < HH; ++h) acc = fmaf(xs[h], w[h], acc);
        sc[e] = acc;
    }
    __syncthreads();
    if (threadIdx.x == 0) {
        float mx = sc[0];
        for (int e = 1; e < EE; ++e) mx = fmaxf(mx, sc[e]);
        float sum = 0.f;
        for (int e = 0; e < EE; ++e) { float v = expf(sc[e] - mx); sc[e] = v; sum += v; }
        float inv = 1.f / sum;
        for (int e = 0; e < EE; ++e) sc[e] *= inv;
        float gs[NGG];
        for (int g = 0; g < NGG; ++g) {
            float m = sc[g*8];
            for (int j = 1; j < 8; ++j) m = fmaxf(m, sc[g*8 + j]);
            gs[g] = m;
        }
        unsigned gsel = 0;
        for (int it = 0; it < TGG; ++it) {
            int best = -1; float bv = -1e30f;
            for (int g = 0; g < NGG; ++g)
                if (!((gsel >> g) & 1u) && gs[g] > bv) { bv = gs[g]; best = g; }
            gsel |= 1u << best;
        }
        unsigned long long used = 0ull;
        for (int kk = 0; kk < KK; ++kk) {
            int best = -1; float bv = -1e30f;
            for (int e = 0; e < EE; ++e) {
                if (!((gsel >> (e >> 3)) & 1u)) continue;
                if ((used >> e) & 1ull) continue;
                if (sc[e] > bv) { bv = sc[e]; best = e; }
            }
            used |= 1ull << best;
            ti[t*KK + kk] = best;
            tw[t*KK + kk] = sc[best];
        }
    }
}

__global__ void zero_cnt_kernel() { if (threadIdx.x < EE) g_cnt[threadIdx.x] = 0; }

__global__ void dispatch_kernel(const int* __restrict__ ti)
{
    int p = blockIdx.x * blockDim.x + threadIdx.x;
    if (p >= NPAIR) return;
    int e = ti[p];
    int r = atomicAdd(&g_cnt[e], 1);
    if (r < CC) g_lists[e*CC + r] = p;
}

// ---------------- swiglu (fp32 out) ----------------
__global__ void swiglu_kernel(const float* __restrict__ g,
                              const float* __restrict__ u,
                              float* __restrict__ h, size_t n4)
{
    size_t i = (size_t)blockIdx.x * blockDim.x + threadIdx.x;
    size_t stride = (size_t)gridDim.x * blockDim.x;
    for (; i < n4; i += stride) {
        float4 gv = ((const float4*)g)[i];
        float4 uv = ((const float4*)u)[i];
        float4 r;
        r.x = (gv.x / (1.f + expf(-gv.x))) * uv.x;
        r.y = (gv.y / (1.f + expf(-gv.y))) * uv.y;
        r.z = (gv.z / (1.f + expf(-gv.z))) * uv.z;
        r.w = (gv.w / (1.f + expf(-gv.w))) * uv.w;
        ((float4*)h)[i] = r;
    }
}

// ======================= split-MMA GEMM, fused fp32->bf16 hi/lo =========
// CTA 128x256, k-chunk 32, 256 threads (8 warps of 64x64), 2-stage smem.
// N-tail predicated (Nd may not divide 256).

#define LDSM4(R, addr) asm volatile( \
    "ldmatrix.sync.aligned.m8n8.x4.shared.b16 {%0,%1,%2,%3},[%4];" \
    : "=r"((R)[0]), "=r"((R)[1]), "=r"((R)[2]), "=r"((R)[3]) : "r"(addr))
#define LDSM2(R, addr) asm volatile( \
    "ldmatrix.sync.aligned.m8n8.x2.shared.b16 {%0,%1},[%2];" \
    : "=r"((R)[0]), "=r"((R)[1]) : "r"(addr))
#define MMA16816(C, A, B) asm volatile( \
    "mma.sync.aligned.m16n8k16.row.col.f32.bf16.bf16.f32 " \
    "{%0,%1,%2,%3},{%4,%5,%6,%7},{%8,%9},{%0,%1,%2,%3};" \
    : "+f"((C)[0]), "+f"((C)[1]), "+f"((C)[2]), "+f"((C)[3]) \
    : "r"((A)[0]), "r"((A)[1]), "r"((A)[2]), "r"((A)[3]), "r"((B)[0]), "r"((B)[1]))

// stage layout (bytes): Ahi 0 (128*80), Alo 10240, Bhi 20480 (256*80), Blo 40960
#define STAGE_B 61440
#define SMEM_TOT (2*STAGE_B + 1024)

__device__ __forceinline__ uint32_t b2u(__nv_bfloat162 v){ return *(uint32_t*)&v; }
__device__ __forceinline__ void cvt8(float4 A, float4 B, uint4& hi, uint4& lo){
    __nv_bfloat162 h0 = __floats2bfloat162_rn(A.x, A.y);
    __nv_bfloat162 h1 = __floats2bfloat162_rn(A.z, A.w);
    __nv_bfloat162 h2 = __floats2bfloat162_rn(B.x, B.y);
    __nv_bfloat162 h3 = __floats2bfloat162_rn(B.z, B.w);
    hi = make_uint4(b2u(h0), b2u(h1), b2u(h2), b2u(h3));
    __nv_bfloat162 l0 = __floats2bfloat162_rn(A.x - __low2float(h0), A.y - __high2float(h0));
    __nv_bfloat162 l1 = __floats2bfloat162_rn(A.z - __low2float(h1), A.w - __high2float(h1));
    __nv_bfloat162 l2 = __floats2bfloat162_rn(B.x - __low2float(h2), B.y - __high2float(h2));
    __nv_bfloat162 l3 = __floats2bfloat162_rn(B.z - __low2float(h3), B.w - __high2float(h3));
    lo = make_uint4(b2u(l0), b2u(l1), b2u(l2), b2u(l3));
}

template<bool GATHER>
__global__ void __launch_bounds__(256)
fg_gemm(const float* __restrict__ A,
        const float* __restrict__ Bg,
        float* __restrict__ Out,
        int Kd, int adiv, long long bstride, int Nd, int nrows_fixed)
{
    extern __shared__ char smem[];
    const int e = blockIdx.z;
    int nrows; const int* mylist = nullptr;
    if (GATHER){ nrows = min(g_cnt[e], CC); mylist = &g_lists[e*CC]; }
    else nrows = nrows_fixed;
    const int m0 = blockIdx.y*128;
    if (m0 >= nrows) return;
    const int n0 = blockIdx.x*256;
    const float* B = Bg + (size_t)e*bstride;

    int* rowA = (int*)(smem + 2*STAGE_B);
    int* rowO = (int*)(smem + 2*STAGE_B + 512);
    const int tid = threadIdx.x;
    if (tid < 128){
        int r = m0 + tid;
        if (r < nrows){
            if (GATHER){ int p = mylist[r]; rowA[tid] = p/adiv; rowO[tid] = p; }
            else       { rowA[tid] = r;      rowO[tid] = r; }
        } else { rowA[tid] = -1; rowO[tid] = -1; }
    }
    __syncthreads();

    // loaders: lrow = tid>>1 (0..127), half = tid&1 (16 floats each phase)
    const int lrow = tid >> 1, half = tid & 1;
    int ra = rowA[lrow]; if (ra < 0) ra = 0;
    int gr0 = n0 + lrow;        if (gr0 >= Nd) gr0 = Nd - 1;
    int gr1 = n0 + 128 + lrow;  if (gr1 >= Nd) gr1 = Nd - 1;
    const float* pa  = A + (size_t)ra*Kd  + half*16;
    const float* pb0 = B + (size_t)gr0*Kd + half*16;
    const float* pb1 = B + (size_t)gr1*Kd + half*16;
    char* sa  = smem + lrow*80 + half*32;            // A-hi; lo at +10240
    char* sb0 = smem + 20480 + lrow*80 + half*32;    // B rows 0-127 hi; lo +20480
    char* sb1 = sb0 + 10240;                          // B rows 128-255

    float4 s0, s1, s2, s3;
    auto ldg = [&](const float* p, int kt){
        const int k0 = kt*32;
        s0 = *(const float4*)(p + k0);
        s1 = *(const float4*)(p + k0 + 4);
        s2 = *(const float4*)(p + k0 + 8);
        s3 = *(const float4*)(p + k0 + 12);
    };
    auto cvt_sts = [&](char* d, int lodelta, int buf){
        uint4 hi, lo;
        char* dd = d + buf*STAGE_B;
        cvt8(s0, s1, hi, lo);
        *(uint4*)(dd)              = hi;
        *(uint4*)(dd + lodelta)    = lo;
        cvt8(s2, s3, hi, lo);
        *(uint4*)(dd + 16)         = hi;
        *(uint4*)(dd + lodelta+16) = lo;
    };

    const int lane = tid & 31;
    const int wid  = tid >> 5;
    const int wm = (wid & 1) * 64;       // warp tile 64x64
    const int wn = (wid >> 1) * 64;

    float acc[4][8][4];
    #pragma unroll
    for (int i = 0; i < 4; ++i)
        #pragma unroll
        for (int j = 0; j < 8; ++j)
            #pragma unroll
            for (int c = 0; c < 4; ++c) acc[i][j][c] = 0.f;

    const uint32_t smem_u = (uint32_t)__cvta_generic_to_shared(smem);
    const uint32_t aoff = (uint32_t)((wm + (lane & 7) + ((lane >> 3) & 1) * 8) * 80
                                     + (lane >> 4) * 16);
    const uint32_t boff = (uint32_t)((wn + (lane & 7)) * 80 + ((lane >> 3) & 1) * 16);

    uint32_t af[4][4], bf[8][2];
    auto ldsm_a = [&](uint32_t base){
        #pragma unroll
        for (int mi = 0; mi < 4; ++mi) LDSM4(af[mi], base + aoff + mi*1280);
    };
    auto ldsm_b = [&](uint32_t base){
        #pragma unroll
        for (int ni = 0; ni < 8; ++ni) LDSM2(bf[ni], base + boff + ni*640);
    };
    auto mma_all = [&](){
        #pragma unroll
        for (int mi = 0; mi < 4; ++mi)
            #pragma unroll
            for (int ni = 0; ni < 8; ++ni)
                MMA16816(acc[mi][ni], af[mi], bf[ni]);
    };

    const int KT = Kd / 32;
    // prologue: fill stage 0 (phased through shared staging regs)
    ldg(pa, 0);  cvt_sts(sa, 10240, 0);
    ldg(pb0, 0); cvt_sts(sb0, 20480, 0);
    ldg(pb1, 0); cvt_sts(sb1, 20480, 0);

    for (int kt = 0; kt < KT; ++kt){
        __syncthreads();
        const uint32_t b = smem_u + (kt & 1) * STAGE_B;
        const int nb = (kt + 1) & 1;
        const bool more = (kt + 1 < KT);
        if (more) ldg(pa, kt + 1);
        // kk = 0  (pass order: ah*bl, ah*bh, al*bh)
        ldsm_b(b + 40960); ldsm_a(b); mma_all();
        if (more){ cvt_sts(sa, 10240, nb); ldg(pb0, kt + 1); }
        ldsm_b(b + 20480); mma_all();
        if (more){ cvt_sts(sb0, 20480, nb); ldg(pb1, kt + 1); }
        ldsm_a(b + 10240); mma_all();
        if (more){ cvt_sts(sb1, 20480, nb); }
        // kk = 1
        ldsm_b(b + 40960 + 32); ldsm_a(b + 32); mma_all();
        ldsm_b(b + 20480 + 32); mma_all();
        ldsm_a(b + 10240 + 32); mma_all();
    }

    // epilogue (N-guarded)
    const int g4 = lane >> 2, tig = lane & 3;
    #pragma unroll
    for (int mi = 0; mi < 4; ++mi){
        int r0 = wm + mi*16 + g4;
        int r1 = r0 + 8;
        int o0 = rowO[r0], o1 = rowO[r1];
        #pragma unroll
        for (int ni = 0; ni < 8; ++ni){
            int cc = n0 + wn + ni*8 + tig*2;
            if (cc < Nd){
                if (o0 >= 0)
                    *(float2*)(Out + (size_t)o0*Nd + cc) = make_float2(acc[mi][ni][0], acc[mi][ni][1]);
                if (o1 >= 0)
                    *(float2*)(Out + (size_t)o1*Nd + cc) = make_float2(acc[mi][ni][2], acc[mi][ni][3]);
            }
        }
    }
}

// ---------------- combine ----------------
__global__ void combine_kernel(const float* __restrict__ ob,
                               const float* __restrict__ ys,
                               const float* __restrict__ tw,
                               float* __restrict__ y)
{
    int t = blockIdx.x;
    for (int c = threadIdx.x; c < HH; c += blockDim.x) {
        float acc = ys[(size_t)t*HH + c];
        #pragma unroll
        for (int k = 0; k < KK; ++k) {
            int p = t*KK + k;
            acc = fmaf(tw[p], ob[(size_t)p*HH + c], acc);
        }
        y[(size_t)t*HH + c] = acc;
    }
}

// ---------------- launch ----------------
extern "C" void kernel_launch(void* const* d_in, const int* in_sizes, int n_in,
                              void* d_out, int out_size)
{
    const float* x  = (const float*)d_in[0];
    const float* gw = (const float*)d_in[1];
    const float* Wg = (const float*)d_in[2];
    const float* Wu = (const float*)d_in[3];
    const float* Wd = (const float*)d_in[4];
    const float* Sg = (const float*)d_in[5];
    const float* Su = (const float*)d_in[6];
    const float* Sd = (const float*)d_in[7];
    float* y = (float*)d_out;

    void *p_ti, *p_tw, *p_g, *p_u, *p_h, *p_ob, *p_gs, *p_us, *p_hs, *p_ys;
    cudaGetSymbolAddress(&p_ti, g_topk_i);  cudaGetSymbolAddress(&p_tw, g_topk_w);
    cudaGetSymbolAddress(&p_g,  g_gbuf);    cudaGetSymbolAddress(&p_u,  g_ubuf);
    cudaGetSymbolAddress(&p_h,  g_hbuf);    cudaGetSymbolAddress(&p_ob, g_outb);
    cudaGetSymbolAddress(&p_gs, g_gs);      cudaGetSymbolAddress(&p_us, g_us);
    cudaGetSymbolAddress(&p_hs, g_hs);      cudaGetSymbolAddress(&p_ys, g_ys);

    cudaFuncSetAttribute(fg_gemm<true>,  cudaFuncAttributeMaxDynamicSharedMemorySize, SMEM_TOT);
    cudaFuncSetAttribute(fg_gemm<false>, cudaFuncAttributeMaxDynamicSharedMemorySize, SMEM_TOT);

    // 1) gate + dispatch
    gate_kernel<<<TT, 64>>>(x, gw, (int*)p_ti, (float*)p_tw);
    zero_cnt_kernel<<<1, 64>>>();
    dispatch_kernel<<<(NPAIR + 255)/256, 256>>>((const int*)p_ti);

    // 2) routed GEMM1: g and u (A = gathered x rows fp32, K = HH, N = MM w/ tail)
    fg_gemm<true><<<dim3((MM+255)/256, CC/128, EE), 256, SMEM_TOT>>>(
        x, Wg, (float*)p_g, HH, KK, (long long)MM*HH, MM, 0);
    fg_gemm<true><<<dim3((MM+255)/256, CC/128, EE), 256, SMEM_TOT>>>(
        x, Wu, (float*)p_u, HH, KK, (long long)MM*HH, MM, 0);

    // 3) swiglu -> h (fp32)
    {
        size_t n4 = (size_t)NPAIR*MM/4;
        swiglu_kernel<<<(int)((n4 + 255)/256), 256>>>((const float*)p_g, (const float*)p_u,
                                                      (float*)p_h, n4);
    }

    // 4) routed GEMM2 (Wd): A = h rows by pair id, K = MM, N = HH
    fg_gemm<true><<<dim3(HH/256, CC/128, EE), 256, SMEM_TOT>>>(
        (const float*)p_h, Wd, (float*)p_ob, MM, 1, (long long)HH*MM, HH, 0);

    // 5) shared expert g,u (K = HH, N = MSS)
    fg_gemm<false><<<dim3(MSS/256, TT/128, 1), 256, SMEM_TOT>>>(
        x, Sg, (float*)p_gs, HH, 1, 0LL, MSS, TT);
    fg_gemm<false><<<dim3(MSS/256, TT/128, 1), 256, SMEM_TOT>>>(
        x, Su, (float*)p_us, HH, 1, 0LL, MSS, TT);

    // 6) shared swiglu
    {
        size_t n4 = (size_t)TT*MSS/4;
        swiglu_kernel<<<(int)((n4 + 255)/256), 256>>>((const float*)p_gs, (const float*)p_us,
                                                      (float*)p_hs, n4);
    }

    // 7) shared GEMM2 (Sd, K = MSS, N = HH)
    fg_gemm<false><<<dim3(HH/256, TT/128, 1), 256, SMEM_TOT>>>(
        (const float*)p_hs, Sd, (float*)p_ys, MSS, 1, 0LL, HH, TT);

    // 8) combine
    combine_kernel<<<TT, 256>>>((const float*)p_ob, (const float*)p_ys,
                                (const float*)p_tw, y);
}

// round 10
// speedup vs baseline: 1.2793x; 1.2793x over previous
#include <cuda_runtime.h>
#include <cuda_bf16.h>
#include <math.h>
#include <stdint.h>

// ---------------- problem constants ----------------
#define TT   4096
#define HH   2048
#define EE   64
#define MM   1408
#define MSS  2816
#define KK   6
#define CC   768
#define NGG  8
#define TGG  3
#define NPAIR (TT*KK)        // 24576

// ---------------- device scratch ----------------
__device__ int   g_topk_i[NPAIR];
__device__ float g_topk_w[NPAIR];
__device__ int   g_cnt[EE];
__device__ int   g_lists[EE*CC];
__device__ float g_gbuf[(size_t)NPAIR*MM];
__device__ float g_ubuf[(size_t)NPAIR*MM];
__device__ float g_hbuf[(size_t)NPAIR*MM];
__device__ float g_outb[(size_t)NPAIR*HH];
__device__ float g_gs[(size_t)TT*MSS];
__device__ float g_us[(size_t)TT*MSS];
__device__ float g_hs[(size_t)TT*MSS];
__device__ float g_ys[(size_t)TT*HH];

// ---------------- gate ----------------
__global__ void gate_kernel(const float* __restrict__ x,
                            const float* __restrict__ gw,
                            int* __restrict__ ti, float* __restrict__ tw)
{
    int t = blockIdx.x;
    __shared__ float xs[HH];
    __shared__ float sc[EE];
    for (int i = threadIdx.x; i < HH; i += 64) xs[i] = x[(size_t)t*HH + i];
    __syncthreads();
    {
        int e = threadIdx.x;
        const float* w = gw + (size_t)e * HH;
        float acc = 0.f;
        #pragma unroll 8
        for (int h = 0; h < HH; ++h) acc = fmaf(xs[h], w[h], acc);
        sc[e] = acc;
    }
    __syncthreads();
    if (threadIdx.x == 0) {
        float mx = sc[0];
        for (int e = 1; e < EE; ++e) mx = fmaxf(mx, sc[e]);
        float sum = 0.f;
        for (int e = 0; e < EE; ++e) { float v = expf(sc[e] - mx); sc[e] = v; sum += v; }
        float inv = 1.f / sum;
        for (int e = 0; e < EE; ++e) sc[e] *= inv;
        float gs[NGG];
        for (int g = 0; g < NGG; ++g) {
            float m = sc[g*8];
            for (int j = 1; j < 8; ++j) m = fmaxf(m, sc[g*8 + j]);
            gs[g] = m;
        }
        unsigned gsel = 0;
        for (int it = 0; it < TGG; ++it) {
            int best = -1; float bv = -1e30f;
            for (int g = 0; g < NGG; ++g)
                if (!((gsel >> g) & 1u) && gs[g] > bv) { bv = gs[g]; best = g; }
            gsel |= 1u << best;
        }
        unsigned long long used = 0ull;
        for (int kk = 0; kk < KK; ++kk) {
            int best = -1; float bv = -1e30f;
            for (int e = 0; e < EE; ++e) {
                if (!((gsel >> (e >> 3)) & 1u)) continue;
                if ((used >> e) & 1ull) continue;
                if (sc[e] > bv) { bv = sc[e]; best = e; }
            }
            used |= 1ull << best;
            ti[t*KK + kk] = best;
            tw[t*KK + kk] = sc[best];
        }
    }
}

__global__ void zero_cnt_kernel() { if (threadIdx.x < EE) g_cnt[threadIdx.x] = 0; }

__global__ void dispatch_kernel(const int* __restrict__ ti)
{
    int p = blockIdx.x * blockDim.x + threadIdx.x;
    if (p >= NPAIR) return;
    int e = ti[p];
    int r = atomicAdd(&g_cnt[e], 1);
    if (r < CC) g_lists[e*CC + r] = p;
}

// ---------------- swiglu (fp32 out) ----------------
__global__ void swiglu_kernel(const float* __restrict__ g,
                              const float* __restrict__ u,
                              float* __restrict__ h, size_t n4)
{
    size_t i = (size_t)blockIdx.x * blockDim.x + threadIdx.x;
    size_t stride = (size_t)gridDim.x * blockDim.x;
    for (; i < n4; i += stride) {
        float4 gv = ((const float4*)g)[i];
        float4 uv = ((const float4*)u)[i];
        float4 r;
        r.x = (gv.x / (1.f + expf(-gv.x))) * uv.x;
        r.y = (gv.y / (1.f + expf(-gv.y))) * uv.y;
        r.z = (gv.z / (1.f + expf(-gv.z))) * uv.z;
        r.w = (gv.w / (1.f + expf(-gv.w))) * uv.w;
        ((float4*)h)[i] = r;
    }
}

// ======================= single-pass tf32 MMA GEMM =========
// CTA 128x128, k-chunk 32 (4 k-steps of 8), 256 threads (8 warps of 64x32),
// 2-stage smem, fused fp32->tf32 (cvt.rna) in the loader, 2 CTAs/SM.

#define LDSM4(R, addr) asm volatile( \
    "ldmatrix.sync.aligned.m8n8.x4.shared.b16 {%0,%1,%2,%3},[%4];" \
    : "=r"((R)[0]), "=r"((R)[1]), "=r"((R)[2]), "=r"((R)[3]) : "r"(addr))
#define MMAT(C, A, B) asm volatile( \
    "mma.sync.aligned.m16n8k8.row.col.f32.tf32.tf32.f32 " \
    "{%0,%1,%2,%3},{%4,%5,%6,%7},{%8,%9},{%0,%1,%2,%3};" \
    : "+f"((C)[0]), "+f"((C)[1]), "+f"((C)[2]), "+f"((C)[3]) \
    : "r"((A)[0]), "r"((A)[1]), "r"((A)[2]), "r"((A)[3]), "r"((B)[0]), "r"((B)[1]))

// row pitch 144B (32 fp32 + 16B pad -> conflict-free ldmatrix), A at 0, B at 18432
#define PITCH   144
#define B_BASE  18432
#define STAGE_B 36864
#define SMEM_TOT (2*STAGE_B + 1024)

__device__ __forceinline__ uint32_t f2tf(float x){
    uint32_t u; asm("cvt.rna.tf32.f32 %0, %1;" : "=r"(u) : "f"(x)); return u;
}
__device__ __forceinline__ uint4 cvt4(float4 v){
    return make_uint4(f2tf(v.x), f2tf(v.y), f2tf(v.z), f2tf(v.w));
}

template<bool GATHER>
__global__ void __launch_bounds__(256, 2)
fg_gemm(const float* __restrict__ A,
        const float* __restrict__ Bg,
        float* __restrict__ Out,
        int Kd, int adiv, long long bstride, int ldo, int nrows_fixed)
{
    extern __shared__ char smem[];
    const int e = blockIdx.z;
    int nrows; const int* mylist = nullptr;
    if (GATHER){ nrows = min(g_cnt[e], CC); mylist = &g_lists[e*CC]; }
    else nrows = nrows_fixed;
    const int m0 = blockIdx.y*128;
    if (m0 >= nrows) return;
    const int n0 = blockIdx.x*128;
    const float* B = Bg + (size_t)e*bstride;

    int* rowA = (int*)(smem + 2*STAGE_B);
    int* rowO = (int*)(smem + 2*STAGE_B + 512);
    const int tid = threadIdx.x;
    if (tid < 128){
        int r = m0 + tid;
        if (r < nrows){
            if (GATHER){ int p = mylist[r]; rowA[tid] = p/adiv; rowO[tid] = p; }
            else       { rowA[tid] = r;      rowO[tid] = r; }
        } else { rowA[tid] = -1; rowO[tid] = -1; }
    }
    __syncthreads();

    // loaders: lrow = tid>>1 (0..127), half = tid&1 (16 floats each phase)
    const int lrow = tid >> 1, half = tid & 1;
    int ra = rowA[lrow]; if (ra < 0) ra = 0;
    const float* pa = A + (size_t)ra*Kd + half*16;
    const float* pb = B + (size_t)(n0 + lrow)*Kd + half*16;
    char* sa = smem + lrow*PITCH + half*64;
    char* sb = smem + B_BASE + lrow*PITCH + half*64;

    float4 s0, s1, s2, s3;     // shared staging for A-phase then B-phase
    auto ldg = [&](const float* p, int kt){
        const int k0 = kt*32;
        s0 = *(const float4*)(p + k0);
        s1 = *(const float4*)(p + k0 + 4);
        s2 = *(const float4*)(p + k0 + 8);
        s3 = *(const float4*)(p + k0 + 12);
    };
    auto cvt_sts = [&](char* d, int buf){
        char* dd = d + buf*STAGE_B;
        *(uint4*)(dd)      = cvt4(s0);
        *(uint4*)(dd + 16) = cvt4(s1);
        *(uint4*)(dd + 32) = cvt4(s2);
        *(uint4*)(dd + 48) = cvt4(s3);
    };

    const int lane = tid & 31;
    const int wid  = tid >> 5;
    const int wm = (wid & 1) * 64;       // warp tile 64x32
    const int wn = (wid >> 1) * 32;

    float acc[4][4][4];
    #pragma unroll
    for (int i = 0; i < 4; ++i)
        #pragma unroll
        for (int j = 0; j < 4; ++j)
            #pragma unroll
            for (int c = 0; c < 4; ++c) acc[i][j][c] = 0.f;

    const uint32_t smem_u = (uint32_t)__cvta_generic_to_shared(smem);
    // A ldmatrix.x4: lanes 0-7 rows 0-7 (k0-3), 8-15 rows 8-15 (k0-3),
    //                16-23 rows 0-7 (k4-7), 24-31 rows 8-15 (k4-7)
    const uint32_t aoff = (uint32_t)((wm + (lane & 15)) * PITCH + (lane >> 4) * 16);
    // B ldmatrix.x4 covers two 8-row n-tiles: lanes 0-7 tile-lo k0-3, 8-15 tile-lo k4-7,
    //                16-23 tile-hi k0-3, 24-31 tile-hi k4-7
    const uint32_t boff = (uint32_t)(B_BASE
        + (wn + (lane & 7) + (lane >> 4) * 8) * PITCH + ((lane >> 3) & 1) * 16);

    // one k-step (k=8): 6x LDSM4 + 16 MMA
    auto mma_ks = [&](uint32_t b, int ks){
        const uint32_t ko = ks * 32;
        uint32_t af[4][4], bf[2][4];
        LDSM4(bf[0], b + boff + ko);            // n-tiles 0,1
        LDSM4(bf[1], b + boff + 2304 + ko);     // n-tiles 2,3 (16 rows * 144B)
        #pragma unroll
        for (int mi = 0; mi < 4; ++mi)
            LDSM4(af[mi], b + aoff + mi*2304 + ko);
        #pragma unroll
        for (int mi = 0; mi < 4; ++mi)
            #pragma unroll
            for (int ni = 0; ni < 4; ++ni)
                MMAT(acc[mi][ni], af[mi], (&bf[ni>>1][(ni&1)*2]));
    };

    const int KT = Kd / 32;
    // prologue: fill stage 0 (phased through shared staging regs)
    ldg(pa, 0); cvt_sts(sa, 0);
    ldg(pb, 0); cvt_sts(sb, 0);

    for (int kt = 0; kt < KT; ++kt){
        __syncthreads();
        const uint32_t b = smem_u + (kt & 1) * STAGE_B;
        const int nb = (kt + 1) & 1;
        const bool more = (kt + 1 < KT);
        if (more) ldg(pa, kt + 1);
        mma_ks(b, 0);
        mma_ks(b, 1);
        if (more){ cvt_sts(sa, nb); ldg(pb, kt + 1); }
        mma_ks(b, 2);
        if (more) cvt_sts(sb, nb);
        mma_ks(b, 3);
    }

    // epilogue
    const int g4 = lane >> 2, tig = lane & 3;
    #pragma unroll
    for (int mi = 0; mi < 4; ++mi){
        int r0 = wm + mi*16 + g4;
        int r1 = r0 + 8;
        int o0 = rowO[r0], o1 = rowO[r1];
        #pragma unroll
        for (int ni = 0; ni < 4; ++ni){
            int cc = n0 + wn + ni*8 + tig*2;
            if (o0 >= 0)
                *(float2*)(Out + (size_t)o0*ldo + cc) = make_float2(acc[mi][ni][0], acc[mi][ni][1]);
            if (o1 >= 0)
                *(float2*)(Out + (size_t)o1*ldo + cc) = make_float2(acc[mi][ni][2], acc[mi][ni][3]);
        }
    }
}

// ---------------- combine ----------------
__global__ void combine_kernel(const float* __restrict__ ob,
                               const float* __restrict__ ys,
                               const float* __restrict__ tw,
                               float* __restrict__ y)
{
    int t = blockIdx.x;
    for (int c = threadIdx.x; c < HH; c += blockDim.x) {
        float acc = ys[(size_t)t*HH + c];
        #pragma unroll
        for (int k = 0; k < KK; ++k) {
            int p = t*KK + k;
            acc = fmaf(tw[p], ob[(size_t)p*HH + c], acc);
        }
        y[(size_t)t*HH + c] = acc;
    }
}

// ---------------- launch ----------------
extern "C" void kernel_launch(void* const* d_in, const int* in_sizes, int n_in,
                              void* d_out, int out_size)
{
    const float* x  = (const float*)d_in[0];
    const float* gw = (const float*)d_in[1];
    const float* Wg = (const float*)d_in[2];
    const float* Wu = (const float*)d_in[3];
    const float* Wd = (const float*)d_in[4];
    const float* Sg = (const float*)d_in[5];
    const float* Su = (const float*)d_in[6];
    const float* Sd = (const float*)d_in[7];
    float* y = (float*)d_out;

    void *p_ti, *p_tw, *p_g, *p_u, *p_h, *p_ob, *p_gs, *p_us, *p_hs, *p_ys;
    cudaGetSymbolAddress(&p_ti, g_topk_i);  cudaGetSymbolAddress(&p_tw, g_topk_w);
    cudaGetSymbolAddress(&p_g,  g_gbuf);    cudaGetSymbolAddress(&p_u,  g_ubuf);
    cudaGetSymbolAddress(&p_h,  g_hbuf);    cudaGetSymbolAddress(&p_ob, g_outb);
    cudaGetSymbolAddress(&p_gs, g_gs);      cudaGetSymbolAddress(&p_us, g_us);
    cudaGetSymbolAddress(&p_hs, g_hs);      cudaGetSymbolAddress(&p_ys, g_ys);

    cudaFuncSetAttribute(fg_gemm<true>,  cudaFuncAttributeMaxDynamicSharedMemorySize, SMEM_TOT);
    cudaFuncSetAttribute(fg_gemm<false>, cudaFuncAttributeMaxDynamicSharedMemorySize, SMEM_TOT);

    // 1) gate + dispatch
    gate_kernel<<<TT, 64>>>(x, gw, (int*)p_ti, (float*)p_tw);
    zero_cnt_kernel<<<1, 64>>>();
    dispatch_kernel<<<(NPAIR + 255)/256, 256>>>((const int*)p_ti);

    // 2) routed GEMM1: g and u (A = gathered x rows fp32, K = HH)
    fg_gemm<true><<<dim3(MM/128, CC/128, EE), 256, SMEM_TOT>>>(
        x, Wg, (float*)p_g, HH, KK, (long long)MM*HH, MM, 0);
    fg_gemm<true><<<dim3(MM/128, CC/128, EE), 256, SMEM_TOT>>>(
        x, Wu, (float*)p_u, HH, KK, (long long)MM*HH, MM, 0);

    // 3) swiglu -> h (fp32)
    {
        size_t n4 = (size_t)NPAIR*MM/4;
        swiglu_kernel<<<(int)((n4 + 255)/256), 256>>>((const float*)p_g, (const float*)p_u,
                                                      (float*)p_h, n4);
    }

    // 4) routed GEMM2 (Wd): A = h rows by pair id, K = MM
    fg_gemm<true><<<dim3(HH/128, CC/128, EE), 256, SMEM_TOT>>>(
        (const float*)p_h, Wd, (float*)p_ob, MM, 1, (long long)HH*MM, HH, 0);

    // 5) shared expert g,u (K = HH)
    fg_gemm<false><<<dim3(MSS/128, TT/128, 1), 256, SMEM_TOT>>>(
        x, Sg, (float*)p_gs, HH, 1, 0LL, MSS, TT);
    fg_gemm<false><<<dim3(MSS/128, TT/128, 1), 256, SMEM_TOT>>>(
        x, Su, (float*)p_us, HH, 1, 0LL, MSS, TT);

    // 6) shared swiglu
    {
        size_t n4 = (size_t)TT*MSS/4;
        swiglu_kernel<<<(int)((n4 + 255)/256), 256>>>((const float*)p_gs, (const float*)p_us,
                                                      (float*)p_hs, n4);
    }

    // 7) shared GEMM2 (Sd, K = MSS)
    fg_gemm<false><<<dim3(HH/128, TT/128, 1), 256, SMEM_TOT>>>(
        (const float*)p_hs, Sd, (float*)p_ys, MSS, 1, 0LL, HH, TT);

    // 8) combine
    combine_kernel<<<TT, 256>>>((const float*)p_ob, (const float*)p_ys,
                                (const float*)p_tw, y);
}